// round 1
// baseline (speedup 1.0000x reference)
#include <cuda_runtime.h>
#include <math.h>

#define NB 8
#define NC 256
#define HD 128
#define HW (HD*HD)
#define HM 512

// scratch (allocation-free rule: __device__ globals)
__device__ __align__(16) float g_m[NB*HW];     // resized mask
__device__ __align__(16) float g_avg[NB*HW];   // m * mean_c(x)
__device__ __align__(16) float g_maxp[NB*HW];  // m * max_c(x)
__device__ __align__(16) float g_s[NB*HW];     // m * sigmoid(conv)

// ---------------------------------------------------------------------------
// Kernel A: antialiased bilinear downsample 512x512 -> 128x128 (half-pixel).
// scale = 1/4 => sample_f = 4i + 1.5, triangle kernel widened by 4:
// raw taps at j = 4i-2..4i+5 with weights {1,3,5,7,7,5,3,1}/8 (pre-norm /4),
// renormalized over in-range taps (matches jax.image.resize antialias=True).
// ---------------------------------------------------------------------------
__global__ void k_resize(const float* __restrict__ masks) {
    int idx = blockIdx.x * blockDim.x + threadIdx.x;
    if (idx >= NB*HW) return;
    int b = idx / HW;
    int r = (idx / HD) % HD;
    int q = idx % HD;
    const float raw[8] = {0.125f,0.375f,0.625f,0.875f,0.875f,0.625f,0.375f,0.125f};
    float wr[8], wc[8]; int jr[8], jc[8];
    float tr = 0.f, tc = 0.f;
#pragma unroll
    for (int k = 0; k < 8; k++) {
        int j = 4*r - 2 + k;
        bool ok = (j >= 0) && (j < HM);
        wr[k] = ok ? raw[k] : 0.f;
        jr[k] = ok ? j : 0;
        tr += wr[k];
        j = 4*q - 2 + k;
        ok = (j >= 0) && (j < HM);
        wc[k] = ok ? raw[k] : 0.f;
        jc[k] = ok ? j : 0;
        tc += wc[k];
    }
    const float* mp = masks + (size_t)b * HM * HM;
    float acc = 0.f;
#pragma unroll
    for (int a = 0; a < 8; a++) {
        float rowacc = 0.f;
#pragma unroll
        for (int bb = 0; bb < 8; bb++)
            rowacc += wc[bb] * __ldg(mp + jr[a]*HM + jc[bb]);
        acc += wr[a] * rowacc;
    }
    g_m[idx] = acc / (tr * tc);
}

// ---------------------------------------------------------------------------
// Kernel B: per (b,h,w): mean and max over C=256 channels of x; premultiply by m.
// Coalesced across hw; 268 MB streaming read.
// ---------------------------------------------------------------------------
__global__ void k_chanstat(const float* __restrict__ x) {
    int idx = blockIdx.x * blockDim.x + threadIdx.x;
    if (idx >= NB*HW) return;
    int b = idx / HW;
    int hw = idx - b * HW;
    const float* xp = x + (size_t)b * NC * HW + hw;
    float s = 0.f, mx = -3.4e38f;
#pragma unroll 8
    for (int c = 0; c < NC; c++) {
        float v = __ldg(xp + (size_t)c * HW);
        s += v;
        mx = fmaxf(mx, v);
    }
    float m = g_m[idx];
    g_avg[idx]  = m * (s * (1.f/NC));
    g_maxp[idx] = m * mx;
}

// ---------------------------------------------------------------------------
// Kernel C: 7x7 conv over 3 channels [avg, max, m] (zero pad 3) -> sigmoid ->
// s = m * atten. 16x16 output tile per block, 22x22x3 smem halo tile.
// ---------------------------------------------------------------------------
__global__ void k_conv(const float* __restrict__ cw) {
    __shared__ float sh[3][22][22];
    __shared__ float wsm[3*49];
    int t = threadIdx.x;                 // 256 threads
    int bx = blockIdx.x & 7;
    int by = (blockIdx.x >> 3) & 7;
    int b  = blockIdx.x >> 6;
    int h0 = by*16 - 3, w0 = bx*16 - 3;
    if (t < 147) wsm[t] = cw[t];
    for (int i = t; i < 22*22; i += 256) {
        int ih = i / 22, iw = i % 22;
        int hh = h0 + ih, ww = w0 + iw;
        bool ok = (hh >= 0) && (hh < HD) && (ww >= 0) && (ww < HD);
        if (ok) {
            int g = b*HW + hh*HD + ww;
            sh[0][ih][iw] = g_avg[g];
            sh[1][ih][iw] = g_maxp[g];
            sh[2][ih][iw] = g_m[g];
        } else {
            sh[0][ih][iw] = 0.f;
            sh[1][ih][iw] = 0.f;
            sh[2][ih][iw] = 0.f;
        }
    }
    __syncthreads();
    int ty = t >> 4, tx = t & 15;
    float acc = 0.f;
#pragma unroll
    for (int c = 0; c < 3; c++)
#pragma unroll
        for (int kh = 0; kh < 7; kh++)
#pragma unroll
            for (int kw = 0; kw < 7; kw++)
                acc += sh[c][ty+kh][tx+kw] * wsm[c*49 + kh*7 + kw];
    float at = 1.f / (1.f + expf(-acc));
    int h = h0 + 3 + ty, w = w0 + 3 + tx;
    int g = b*HW + h*HD + w;
    g_s[g] = g_m[g] * at;
}

// ---------------------------------------------------------------------------
// Kernel D: per (b,c) channel: out = x*s; InstanceNorm (population var) + affine;
// relu(5*rn). One block per channel; channel staged in 64KB smem so the
// normalize pass is DRAM-free. 512 threads, float4 I/O.
// ---------------------------------------------------------------------------
__global__ void k_norm(const float* __restrict__ x,
                       const float* __restrict__ gamma,
                       const float* __restrict__ beta,
                       float* __restrict__ out) {
    extern __shared__ float4 sh4[];      // 4096 float4 = 64KB
    int bc = blockIdx.x;
    int b = bc >> 8, c = bc & 255;
    const float4* xp = (const float4*)(x + (size_t)bc * HW);
    const float4* sp = (const float4*)(g_s + (size_t)b * HW);
    float4* op = (float4*)(out + (size_t)bc * HW);

    float sum = 0.f, ss = 0.f;
#pragma unroll
    for (int it = 0; it < 8; it++) {
        int i = it*512 + threadIdx.x;
        float4 xv = xp[i], sv = sp[i];
        float4 v = make_float4(xv.x*sv.x, xv.y*sv.y, xv.z*sv.z, xv.w*sv.w);
        sh4[i] = v;
        sum += (v.x + v.y) + (v.z + v.w);
        ss  += v.x*v.x + v.y*v.y + v.z*v.z + v.w*v.w;
    }
    // block reduction: warp shfl then 16 partials
    for (int o = 16; o > 0; o >>= 1) {
        sum += __shfl_down_sync(0xffffffffu, sum, o);
        ss  += __shfl_down_sync(0xffffffffu, ss,  o);
    }
    __shared__ float rs[16], rq[16];
    __shared__ float s_g, s_b;
    int wid = threadIdx.x >> 5, lid = threadIdx.x & 31;
    if (lid == 0) { rs[wid] = sum; rq[wid] = ss; }
    __syncthreads();
    if (threadIdx.x == 0) {
        float S = 0.f, Q = 0.f;
#pragma unroll
        for (int i = 0; i < 16; i++) { S += rs[i]; Q += rq[i]; }
        float mu  = S * (1.f/HW);
        float var = Q * (1.f/HW) - mu*mu;
        float inv = rsqrtf(var + 1e-5f);
        float gg  = gamma[c] * inv;
        s_g = 5.f * gg;
        s_b = 5.f * (beta[c] - mu * gg);
    }
    __syncthreads();
    float gg = s_g, bb = s_b;
#pragma unroll
    for (int it = 0; it < 8; it++) {
        int i = it*512 + threadIdx.x;
        float4 v = sh4[i];
        op[i] = make_float4(fmaxf(0.f, v.x*gg + bb),
                            fmaxf(0.f, v.y*gg + bb),
                            fmaxf(0.f, v.z*gg + bb),
                            fmaxf(0.f, v.w*gg + bb));
    }
}

extern "C" void kernel_launch(void* const* d_in, const int* in_sizes, int n_in,
                              void* d_out, int out_size) {
    const float* x     = (const float*)d_in[0];
    const float* masks = (const float*)d_in[1];
    const float* cw    = (const float*)d_in[2];
    const float* gamma = (const float*)d_in[3];
    const float* beta  = (const float*)d_in[4];
    float* out = (float*)d_out;

    k_resize  <<<(NB*HW + 255)/256, 256>>>(masks);
    k_chanstat<<<(NB*HW + 255)/256, 256>>>(x);
    k_conv    <<<NB*64, 256>>>(cw);
    cudaFuncSetAttribute(k_norm, cudaFuncAttributeMaxDynamicSharedMemorySize, 65536);
    k_norm    <<<NB*NC, 512, 65536>>>(x, gamma, beta, out);
}

// round 2
// speedup vs baseline: 1.0086x; 1.0086x over previous
#include <cuda_runtime.h>
#include <math.h>

#define NB 8
#define NC 256
#define HD 128
#define HW (HD*HD)
#define HM 512

// scratch (allocation-free rule: __device__ globals)
__device__ __align__(16) float g_m[NB*HW];     // resized mask
__device__ __align__(16) float g_avg[NB*HW];   // m * mean_c(x)
__device__ __align__(16) float g_maxp[NB*HW];  // m * max_c(x)
__device__ __align__(16) float g_s[NB*HW];     // m * sigmoid(conv)

// ---------------------------------------------------------------------------
// Kernel A: antialiased bilinear downsample 512x512 -> 128x128 (half-pixel).
// 8-tap triangle kernel {1,3,5,7,7,5,3,1}/8 per dim, renormalized at edges.
// ---------------------------------------------------------------------------
__global__ void k_resize(const float* __restrict__ masks) {
    int idx = blockIdx.x * blockDim.x + threadIdx.x;
    if (idx >= NB*HW) return;
    int b = idx / HW;
    int r = (idx / HD) % HD;
    int q = idx % HD;
    const float raw[8] = {0.125f,0.375f,0.625f,0.875f,0.875f,0.625f,0.375f,0.125f};
    float wr[8], wc[8]; int jr[8], jc[8];
    float tr = 0.f, tc = 0.f;
#pragma unroll
    for (int k = 0; k < 8; k++) {
        int j = 4*r - 2 + k;
        bool ok = (j >= 0) && (j < HM);
        wr[k] = ok ? raw[k] : 0.f;
        jr[k] = ok ? j : 0;
        tr += wr[k];
        j = 4*q - 2 + k;
        ok = (j >= 0) && (j < HM);
        wc[k] = ok ? raw[k] : 0.f;
        jc[k] = ok ? j : 0;
        tc += wc[k];
    }
    const float* mp = masks + (size_t)b * HM * HM;
    float acc = 0.f;
#pragma unroll
    for (int a = 0; a < 8; a++) {
        float rowacc = 0.f;
#pragma unroll
        for (int bb = 0; bb < 8; bb++)
            rowacc += wc[bb] * __ldg(mp + jr[a]*HM + jc[bb]);
        acc += wr[a] * rowacc;
    }
    g_m[idx] = acc / (tr * tc);
}

// ---------------------------------------------------------------------------
// Kernel B: per (b,h,w): mean and max over C=256 channels; premultiply by m.
// float2 per thread (2 independent accumulator chains), unroll 16 for MLP.
// ---------------------------------------------------------------------------
__global__ void k_chanstat(const float* __restrict__ x) {
    int idx = blockIdx.x * blockDim.x + threadIdx.x;   // over NB*HW/2
    if (idx >= NB*(HW/2)) return;
    int b   = idx / (HW/2);
    int hw2 = idx - b * (HW/2);
    const float2* xp = (const float2*)x + (size_t)b * NC * (HW/2) + hw2;
    float sx = 0.f, sy = 0.f;
    float mxx = -3.4e38f, mxy = -3.4e38f;
#pragma unroll 16
    for (int c = 0; c < NC; c++) {
        float2 v = __ldg(xp + (size_t)c * (HW/2));
        sx += v.x; sy += v.y;
        mxx = fmaxf(mxx, v.x);
        mxy = fmaxf(mxy, v.y);
    }
    float2 m = ((const float2*)g_m)[idx];
    ((float2*)g_avg)[idx]  = make_float2(m.x * (sx * (1.f/NC)), m.y * (sy * (1.f/NC)));
    ((float2*)g_maxp)[idx] = make_float2(m.x * mxx, m.y * mxy);
}

// ---------------------------------------------------------------------------
// Kernel C: 7x7 conv over [avg, max, m] (zero pad 3) -> sigmoid -> s = m*atten.
// 16x16 output tile per block, 22x22x3 smem halo tile.
// ---------------------------------------------------------------------------
__global__ void k_conv(const float* __restrict__ cw) {
    __shared__ float sh[3][22][22];
    __shared__ float wsm[3*49];
    int t = threadIdx.x;                 // 256 threads
    int bx = blockIdx.x & 7;
    int by = (blockIdx.x >> 3) & 7;
    int b  = blockIdx.x >> 6;
    int h0 = by*16 - 3, w0 = bx*16 - 3;
    if (t < 147) wsm[t] = cw[t];
    for (int i = t; i < 22*22; i += 256) {
        int ih = i / 22, iw = i % 22;
        int hh = h0 + ih, ww = w0 + iw;
        bool ok = (hh >= 0) && (hh < HD) && (ww >= 0) && (ww < HD);
        if (ok) {
            int g = b*HW + hh*HD + ww;
            sh[0][ih][iw] = g_avg[g];
            sh[1][ih][iw] = g_maxp[g];
            sh[2][ih][iw] = g_m[g];
        } else {
            sh[0][ih][iw] = 0.f;
            sh[1][ih][iw] = 0.f;
            sh[2][ih][iw] = 0.f;
        }
    }
    __syncthreads();
    int ty = t >> 4, tx = t & 15;
    float acc = 0.f;
#pragma unroll
    for (int c = 0; c < 3; c++)
#pragma unroll
        for (int kh = 0; kh < 7; kh++)
#pragma unroll
            for (int kw = 0; kw < 7; kw++)
                acc += sh[c][ty+kh][tx+kw] * wsm[c*49 + kh*7 + kw];
    float at = 1.f / (1.f + expf(-acc));
    int h = h0 + 3 + ty, w = w0 + 3 + tx;
    int g = b*HW + h*HD + w;
    g_s[g] = g_m[g] * at;
}

// ---------------------------------------------------------------------------
// Kernel D: per (b,c): out = relu(5 * IN(x*s)). Two-pass, NO smem staging:
// phase 1 streams x,s (DRAM) for sum/sumsq; phase 2 re-reads the same 64KB
// channel (L2-resident between phases) and writes out. Full occupancy.
// ---------------------------------------------------------------------------
__global__ void k_norm(const float* __restrict__ x,
                       const float* __restrict__ gamma,
                       const float* __restrict__ beta,
                       float* __restrict__ out) {
    int bc = blockIdx.x;
    int b = bc >> 8, c = bc & 255;
    const float4* xp = (const float4*)(x + (size_t)bc * HW);
    const float4* sp = (const float4*)(g_s + (size_t)b * HW);
    float4* op = (float4*)(out + (size_t)bc * HW);

    float sum = 0.f, ss = 0.f;
#pragma unroll
    for (int it = 0; it < 8; it++) {
        int i = it*512 + threadIdx.x;
        float4 xv = xp[i], sv = sp[i];
        float vx = xv.x*sv.x, vy = xv.y*sv.y, vz = xv.z*sv.z, vw = xv.w*sv.w;
        sum += (vx + vy) + (vz + vw);
        ss  += vx*vx + vy*vy + vz*vz + vw*vw;
    }
    // block reduction: warp shfl then 16 partials
    for (int o = 16; o > 0; o >>= 1) {
        sum += __shfl_down_sync(0xffffffffu, sum, o);
        ss  += __shfl_down_sync(0xffffffffu, ss,  o);
    }
    __shared__ float rs[16], rq[16];
    __shared__ float s_g, s_b;
    int wid = threadIdx.x >> 5, lid = threadIdx.x & 31;
    if (lid == 0) { rs[wid] = sum; rq[wid] = ss; }
    __syncthreads();
    if (threadIdx.x == 0) {
        float S = 0.f, Q = 0.f;
#pragma unroll
        for (int i = 0; i < 16; i++) { S += rs[i]; Q += rq[i]; }
        float mu  = S * (1.f/HW);
        float var = Q * (1.f/HW) - mu*mu;
        float inv = rsqrtf(var + 1e-5f);
        float gg  = gamma[c] * inv;
        s_g = 5.f * gg;
        s_b = 5.f * (beta[c] - mu * gg);
    }
    __syncthreads();
    float gg = s_g, bb = s_b;
#pragma unroll
    for (int it = 0; it < 8; it++) {
        int i = it*512 + threadIdx.x;
        float4 xv = xp[i], sv = sp[i];   // L2 hit (same 64KB read in phase 1)
        op[i] = make_float4(fmaxf(0.f, xv.x*sv.x*gg + bb),
                            fmaxf(0.f, xv.y*sv.y*gg + bb),
                            fmaxf(0.f, xv.z*sv.z*gg + bb),
                            fmaxf(0.f, xv.w*sv.w*gg + bb));
    }
}

extern "C" void kernel_launch(void* const* d_in, const int* in_sizes, int n_in,
                              void* d_out, int out_size) {
    const float* x     = (const float*)d_in[0];
    const float* masks = (const float*)d_in[1];
    const float* cw    = (const float*)d_in[2];
    const float* gamma = (const float*)d_in[3];
    const float* beta  = (const float*)d_in[4];
    float* out = (float*)d_out;

    k_resize  <<<(NB*HW + 255)/256, 256>>>(masks);
    k_chanstat<<<(NB*(HW/2) + 127)/128, 128>>>(x);
    k_conv    <<<NB*64, 256>>>(cw);
    k_norm    <<<NB*NC, 512>>>(x, gamma, beta, out);
}